// round 5
// baseline (speedup 1.0000x reference)
#include <cuda_runtime.h>
#include <cuda_bf16.h>
#include <math.h>

// Problem constants (shapes fixed by the dataset)
#define MAXM 50000
#define MAXE 600000
#define MAXN 100000
// D = 128 floats = 32 float4 per row

// ---------------- device scratch (static: no allocations allowed) -----------
__device__ float  g_deg[MAXM];
__device__ float  g_dis[MAXM];
__device__ float  g_nval[MAXE];
__device__ int    g_cnt[MAXM];
__device__ int    g_rowptr[MAXM + 1];
__device__ int    g_cursor[MAXM];
__device__ int    g_ccol[MAXE];
__device__ float  g_cval[MAXE];
__device__ float4 g_s0[MAXM * 32];   // 25.6 MB
__device__ float4 g_s1[MAXM * 32];   // 25.6 MB
__device__ int    g_srcmap[MAXN];

// ---------------- preprocessing kernels ------------------------------------
__global__ void k_init(int M, int N) {
    int i = blockIdx.x * blockDim.x + threadIdx.x;
    if (i < M) { g_deg[i] = 0.f; g_cnt[i] = 0; }
    if (i < N) g_srcmap[i] = -1;
}

__global__ void k_degcnt(const int* __restrict__ row,
                         const float* __restrict__ val, int E) {
    int e = blockIdx.x * blockDim.x + threadIdx.x;
    if (e < E) {
        int r = row[e];
        atomicAdd(&g_deg[r], val[e]);
        atomicAdd(&g_cnt[r], 1);
    }
}

__global__ void k_dis(int M) {
    int i = blockIdx.x * blockDim.x + threadIdx.x;
    if (i < M) g_dis[i] = rsqrtf(g_deg[i] + 1e-8f);
}

__global__ void k_nval(const int* __restrict__ row, const int* __restrict__ col,
                       const float* __restrict__ val, int E) {
    int e = blockIdx.x * blockDim.x + threadIdx.x;
    if (e < E) g_nval[e] = val[e] * g_dis[row[e]] * g_dis[col[e]];
}

// single-block exclusive scan of g_cnt -> g_rowptr / g_cursor
__global__ void k_scan(int M, int E) {
    __shared__ int sums[1024];
    int t = threadIdx.x;
    int CH = (M + 1023) >> 10;
    int b = t * CH;
    int s = 0;
    for (int i = 0; i < CH; i++) {
        int idx = b + i;
        if (idx < M) s += g_cnt[idx];
    }
    sums[t] = s;
    __syncthreads();
    // Hillis-Steele inclusive scan
    for (int off = 1; off < 1024; off <<= 1) {
        int v = (t >= off) ? sums[t - off] : 0;
        __syncthreads();
        sums[t] += v;
        __syncthreads();
    }
    int excl = (t == 0) ? 0 : sums[t - 1];
    for (int i = 0; i < CH; i++) {
        int idx = b + i;
        if (idx < M) {
            g_rowptr[idx] = excl;
            g_cursor[idx] = excl;
            excl += g_cnt[idx];
        }
    }
    if (t == 0) g_rowptr[M] = E;
}

__global__ void k_scatter(const int* __restrict__ row, const int* __restrict__ col,
                          int E) {
    int e = blockIdx.x * blockDim.x + threadIdx.x;
    if (e < E) {
        int r = row[e];
        int p = atomicAdd(&g_cursor[r], 1);
        g_ccol[p] = col[e];
        g_cval[p] = g_nval[e];
    }
}

// subset gather: s0[m] = features[index[m]]; srcmap[index[m]] = m
__global__ void k_gather0(const float* __restrict__ features,
                          const int* __restrict__ index, int M) {
    int i = blockIdx.x * blockDim.x + threadIdx.x;
    if (i < M * 32) {
        int m = i >> 5;
        int q = i & 31;
        int src = index[m];
        if (q == 0) g_srcmap[src] = m;
        g_s0[m * 32 + q] = ((const float4*)features)[(size_t)src * 32 + q];
    }
}

// ---------------- SpMM: one warp per row, float4 per lane -------------------
__global__ void k_spmm(int srcsel, int M) {
    const float4* __restrict__ src = srcsel ? (const float4*)g_s1 : (const float4*)g_s0;
    float4* __restrict__ dst       = srcsel ? (float4*)g_s0       : (float4*)g_s1;
    int gw   = (blockIdx.x * blockDim.x + threadIdx.x) >> 5;
    int lane = threadIdx.x & 31;
    if (gw >= M) return;
    int e   = g_rowptr[gw];
    int end = g_rowptr[gw + 1];
    float4 acc = make_float4(0.f, 0.f, 0.f, 0.f);
    // 2 independent gathers in flight per iteration
    for (; e + 2 <= end; e += 2) {
        int   c0 = __ldg(g_ccol + e);
        int   c1 = __ldg(g_ccol + e + 1);
        float w0 = __ldg(g_cval + e);
        float w1 = __ldg(g_cval + e + 1);
        float4 v0 = __ldg(src + c0 * 32 + lane);
        float4 v1 = __ldg(src + c1 * 32 + lane);
        acc.x = fmaf(w0, v0.x, acc.x); acc.y = fmaf(w0, v0.y, acc.y);
        acc.z = fmaf(w0, v0.z, acc.z); acc.w = fmaf(w0, v0.w, acc.w);
        acc.x = fmaf(w1, v1.x, acc.x); acc.y = fmaf(w1, v1.y, acc.y);
        acc.z = fmaf(w1, v1.z, acc.z); acc.w = fmaf(w1, v1.w, acc.w);
    }
    if (e < end) {
        int   c0 = __ldg(g_ccol + e);
        float w0 = __ldg(g_cval + e);
        float4 v0 = __ldg(src + c0 * 32 + lane);
        acc.x = fmaf(w0, v0.x, acc.x); acc.y = fmaf(w0, v0.y, acc.y);
        acc.z = fmaf(w0, v0.z, acc.z); acc.w = fmaf(w0, v0.w, acc.w);
    }
    dst[gw * 32 + lane] = acc;
}

// ---------------- fused MLP head --------------------------------------------
// 64 nodes per block, 256 threads. x staged in smem [64][132], weights from L1.
// GEMM1: thread = (nq=t/32 -> 8 nodes, jl=t%32 -> outputs jl & jl+32)
__device__ __forceinline__ float leaky(float v) { return v > 0.f ? v : 0.01f * v; }

__global__ void __launch_bounds__(256) k_mlp(
    const float* __restrict__ feat,
    const float* __restrict__ W1, const float* __restrict__ b1,
    const float* __restrict__ W2, const float* __restrict__ b2,
    const float* __restrict__ W3, const float* __restrict__ b3,
    const float* __restrict__ W4,
    float* __restrict__ out, int Ntot)
{
    __shared__ float xs[64 * 132];            // 33.8 KB, reused for h1/h2/h3
    float* h1s = xs;                          // [64][68]  (after sync)
    float* h2s = xs + 64 * 68;                // [64][36]
    float* h3s = xs + 64 * 68 + 64 * 36;      // [64][24]

    int t  = threadIdx.x;
    int nb = blockIdx.x * 64;

    // ---- stage x: final features row per node (s1 for propagated nodes) ----
    for (int i = t; i < 64 * 32; i += 256) {
        int n  = i >> 5;
        int c4 = i & 31;
        int gn = nb + n;
        float4 v = make_float4(0.f, 0.f, 0.f, 0.f);
        if (gn < Ntot) {
            int sm_ = g_srcmap[gn];
            const float4* src = (sm_ >= 0) ? ((const float4*)g_s1) + (size_t)sm_ * 32
                                           : ((const float4*)feat) + (size_t)gn * 32;
            v = __ldg(src + c4);
        }
        *(float4*)&xs[n * 132 + c4 * 4] = v;
    }
    __syncthreads();

    int nq = t >> 5, jl = t & 31, n0 = nq * 8;

    // ---- GEMM1: [64x128] @ W1[128x64] + b1, leaky ----
    float a0[8], a1[8];
#pragma unroll
    for (int i = 0; i < 8; i++) { a0[i] = 0.f; a1[i] = 0.f; }
#pragma unroll 4
    for (int k = 0; k < 128; k++) {
        float w0 = __ldg(W1 + k * 64 + jl);
        float w1 = __ldg(W1 + k * 64 + jl + 32);
#pragma unroll
        for (int i = 0; i < 8; i++) {
            float xv = xs[(n0 + i) * 132 + k];
            a0[i] = fmaf(xv, w0, a0[i]);
            a1[i] = fmaf(xv, w1, a1[i]);
        }
    }
    __syncthreads();   // done reading xs; h1s aliases it
    {
        float bb0 = __ldg(b1 + jl), bb1 = __ldg(b1 + jl + 32);
#pragma unroll
        for (int i = 0; i < 8; i++) {
            h1s[(n0 + i) * 68 + jl]      = leaky(a0[i] + bb0);
            h1s[(n0 + i) * 68 + jl + 32] = leaky(a1[i] + bb1);
        }
    }
    __syncthreads();

    // ---- GEMM2: [64x64] @ W2[64x32] + b2, leaky ----
    float a2[8];
#pragma unroll
    for (int i = 0; i < 8; i++) a2[i] = 0.f;
#pragma unroll 4
    for (int k = 0; k < 64; k++) {
        float w = __ldg(W2 + k * 32 + jl);
#pragma unroll
        for (int i = 0; i < 8; i++)
            a2[i] = fmaf(h1s[(n0 + i) * 68 + k], w, a2[i]);
    }
    __syncthreads();
    {
        float bb = __ldg(b2 + jl);
#pragma unroll
        for (int i = 0; i < 8; i++)
            h2s[(n0 + i) * 36 + jl] = leaky(a2[i] + bb);
    }
    __syncthreads();

    // ---- GEMM3: [64x32] @ W3[32x21] + b3, leaky ----
    float a3[8];
#pragma unroll
    for (int i = 0; i < 8; i++) a3[i] = 0.f;
    if (jl < 21) {
#pragma unroll 4
        for (int k = 0; k < 32; k++) {
            float w = __ldg(W3 + k * 21 + jl);
#pragma unroll
            for (int i = 0; i < 8; i++)
                a3[i] = fmaf(h2s[(n0 + i) * 36 + k], w, a3[i]);
        }
    }
    __syncthreads();
    if (jl < 21) {
        float bb = __ldg(b3 + jl);
#pragma unroll
        for (int i = 0; i < 8; i++)
            h3s[(n0 + i) * 24 + jl] = leaky(a3[i] + bb);
    }
    __syncthreads();

    // ---- GEMM4 + sigmoid: [64x21] @ W4[21x1] ----
    if (t < 64) {
        int gn = nb + t;
        if (gn < Ntot) {
            float s = 0.f;
#pragma unroll
            for (int k = 0; k < 21; k++)
                s = fmaf(h3s[t * 24 + k], __ldg(W4 + k), s);
            out[gn] = 1.f / (1.f + expf(-s));
        }
    }
}

// ---------------- launch -----------------------------------------------------
extern "C" void kernel_launch(void* const* d_in, const int* in_sizes, int n_in,
                              void* d_out, int out_size) {
    const float* features = (const float*)d_in[0];
    const int*   index    = (const int*)d_in[1];
    const int*   erow     = (const int*)d_in[2];
    const int*   ecol     = (const int*)d_in[3];
    const float* eval_    = (const float*)d_in[4];
    const float* W1 = (const float*)d_in[5];
    const float* b1 = (const float*)d_in[6];
    const float* W2 = (const float*)d_in[7];
    const float* b2 = (const float*)d_in[8];
    const float* W3 = (const float*)d_in[9];
    const float* b3 = (const float*)d_in[10];
    const float* W4 = (const float*)d_in[11];

    int M = in_sizes[1];
    int E = in_sizes[2];
    int N = out_size;            // [N, 1] fp32 output
    float* out = (float*)d_out;

    const int TB = 256;
    k_init   <<<(N + TB - 1) / TB, TB>>>(M, N);
    k_degcnt <<<(E + TB - 1) / TB, TB>>>(erow, eval_, E);
    k_dis    <<<(M + TB - 1) / TB, TB>>>(M);
    k_nval   <<<(E + TB - 1) / TB, TB>>>(erow, ecol, eval_, E);
    k_scan   <<<1, 1024>>>(M, E);
    k_scatter<<<(E + TB - 1) / TB, TB>>>(erow, ecol, E);
    k_gather0<<<(M * 32 + TB - 1) / TB, TB>>>(features, index, M);

    int spmmBlocks = (M * 32 + TB - 1) / TB;
    k_spmm<<<spmmBlocks, TB>>>(0, M);   // s0 -> s1
    k_spmm<<<spmmBlocks, TB>>>(1, M);   // s1 -> s0
    k_spmm<<<spmmBlocks, TB>>>(0, M);   // s0 -> s1  (final in s1)

    k_mlp<<<(N + 63) / 64, 256>>>(features, W1, b1, W2, b2, W3, b3, W4, out, N);
}